// round 1
// baseline (speedup 1.0000x reference)
#include <cuda_runtime.h>
#include <cuda_bf16.h>
#include <cstdint>

#define NN 100000
#define EE 1600000
#define DD 128
#define LL 4
#define LN_EPS 1e-5f

// ---------------- device scratch (static, allocation-free) ----------------
__device__ int   g_deg[NN];
__device__ int   g_cnt[NN];
__device__ int   g_row_ptr[NN + 1];
__device__ int   g_csr_src[EE];
__device__ float g_bufA[NN * DD];
__device__ float g_bufB[NN * DD];
__device__ float g_agg[NN * DD];
__device__ float g_wperm[32 * 32 * 32];   // fragment-ordered tf32 weights (stored as float bits)

// ---------------- helpers ----------------
__device__ __forceinline__ uint32_t f2tf32(float f) {
    uint32_t r;
    asm("cvt.rna.tf32.f32 %0, %1;" : "=r"(r) : "f"(f));
    return r;
}

__device__ __forceinline__ void mma_tf32(float c[4],
                                         uint32_t a0, uint32_t a1, uint32_t a2, uint32_t a3,
                                         uint32_t b0, uint32_t b1) {
    asm volatile(
        "mma.sync.aligned.m16n8k8.row.col.f32.tf32.tf32.f32 "
        "{%0,%1,%2,%3},{%4,%5,%6,%7},{%8,%9},{%0,%1,%2,%3};\n"
        : "+f"(c[0]), "+f"(c[1]), "+f"(c[2]), "+f"(c[3])
        : "r"(a0), "r"(a1), "r"(a2), "r"(a3), "r"(b0), "r"(b1));
}

__device__ __forceinline__ void add4(float4& a, const float4 b) {
    a.x += b.x; a.y += b.y; a.z += b.z; a.w += b.w;
}

// ---------------- preprocessing kernels ----------------
__global__ void zero_kernel() {
    int i = blockIdx.x * blockDim.x + threadIdx.x;
    if (i < NN) { g_deg[i] = 0; g_cnt[i] = 0; }
}

__global__ void hist_kernel(const int* __restrict__ dst) {
    int e = blockIdx.x * blockDim.x + threadIdx.x;
    if (e < EE) atomicAdd(&g_deg[dst[e]], 1);
}

// exclusive scan of g_deg -> g_row_ptr, single block of 1024 threads
__global__ void scan_kernel() {
    __shared__ int wsum[32];
    __shared__ int sh_carry;
    int tid = threadIdx.x, lane = tid & 31, warp = tid >> 5;
    if (tid == 0) sh_carry = 0;
    __syncthreads();
    for (int base = 0; base < NN; base += 1024) {
        int i = base + tid;
        int v = (i < NN) ? g_deg[i] : 0;
        int x = v;
        #pragma unroll
        for (int m = 1; m < 32; m <<= 1) {
            int y = __shfl_up_sync(0xffffffffu, x, m);
            if (lane >= m) x += y;
        }
        if (lane == 31) wsum[warp] = x;
        __syncthreads();
        if (warp == 0) {
            int s = wsum[lane];
            #pragma unroll
            for (int m = 1; m < 32; m <<= 1) {
                int y = __shfl_up_sync(0xffffffffu, s, m);
                if (lane >= m) s += y;
            }
            wsum[lane] = s;
        }
        __syncthreads();
        int off = (warp > 0 ? wsum[warp - 1] : 0) + sh_carry;
        if (i < NN) g_row_ptr[i] = off + x - v;
        int total = wsum[31];
        __syncthreads();
        if (tid == 0) sh_carry += total;
        __syncthreads();
    }
    if (threadIdx.x == 0) g_row_ptr[NN] = sh_carry;
}

__global__ void scatter_kernel(const int* __restrict__ src, const int* __restrict__ dst) {
    int e = blockIdx.x * blockDim.x + threadIdx.x;
    if (e < EE) {
        int d = dst[e];
        int pos = g_row_ptr[d] + atomicAdd(&g_cnt[d], 1);
        g_csr_src[pos] = src[e];
    }
}

// ---------------- aggregation: agg[i] = sum_{e: dst=i} h[src_e] ----------------
__global__ void agg_kernel(const float* __restrict__ h) {
    int gw = (blockIdx.x * blockDim.x + threadIdx.x) >> 5;
    int lane = threadIdx.x & 31;
    if (gw >= NN) return;
    int beg = g_row_ptr[gw], end = g_row_ptr[gw + 1];
    const float4* __restrict__ h4 = (const float4*)h;
    float4 a0 = make_float4(0.f, 0.f, 0.f, 0.f);
    float4 a1 = a0, a2 = a0, a3 = a0;
    int e = beg;
    for (; e + 4 <= end; e += 4) {
        int s0 = g_csr_src[e + 0];
        int s1 = g_csr_src[e + 1];
        int s2 = g_csr_src[e + 2];
        int s3 = g_csr_src[e + 3];
        float4 v0 = __ldg(&h4[s0 * 32 + lane]);
        float4 v1 = __ldg(&h4[s1 * 32 + lane]);
        float4 v2 = __ldg(&h4[s2 * 32 + lane]);
        float4 v3 = __ldg(&h4[s3 * 32 + lane]);
        add4(a0, v0); add4(a1, v1); add4(a2, v2); add4(a3, v3);
    }
    for (; e < end; ++e) {
        int s0 = g_csr_src[e];
        add4(a0, __ldg(&h4[s0 * 32 + lane]));
    }
    add4(a0, a1); add4(a2, a3); add4(a0, a2);
    ((float4*)g_agg)[gw * 32 + lane] = a0;
}

// ---------------- weight permutation (fragment order, tf32-rounded) ----------------
// g_wperm[(kk*32+lane)*32 + j] = Wcomb[kk*8 + tig + (j&1)*4][(j>>1)*8 + g]
// where Wcomb rows 0..127 = W_rel, 128..255 = W_root; lane = g*4+tig
__global__ void wprep_kernel(const float* __restrict__ W_rel_l, const float* __restrict__ W_root_l) {
    int idx = blockIdx.x * blockDim.x + threadIdx.x;  // 0..32767
    int kk = idx >> 10;
    int lane = (idx >> 5) & 31;
    int j = idx & 31;
    int g = lane >> 2, tig = lane & 3;
    int krow = kk * 8 + tig + (j & 1) * 4;
    int col = (j >> 1) * 8 + g;
    float v = (krow < 128) ? W_rel_l[krow * 128 + col] : W_root_l[(krow - 128) * 128 + col];
    uint32_t t = f2tf32(v);
    g_wperm[idx] = __uint_as_float(t);
}

// ---------------- fused GEMM + bias + residual + ReLU + LayerNorm ----------------
// out[M,128] = agg @ W_rel + bias + h @ W_root  (K=256 stacked, tf32 mma)
struct GSmem {
    float w[32][32][36];   // [kk][lane][j] padded 32->36 for conflict-free LDS.128
    float a[128][132];     // A tile, padded stride
    float bias[128];
    float gamma[128];
    float beta[128];
};

__global__ void __launch_bounds__(256, 1)
gemm_kernel(const float* __restrict__ Hin,
            const float* __restrict__ bias,
            const float* __restrict__ gamma,
            const float* __restrict__ beta,
            float* __restrict__ out,
            int do_ln, int do_resid) {
    extern __shared__ char smem_raw[];
    GSmem& s = *(GSmem*)smem_raw;
    int tid = threadIdx.x, warp = tid >> 5, lane = tid & 31;
    int g = lane >> 2, tig = lane & 3;

    // load fragment-ordered weights
    for (int i = tid; i < 32768; i += 256) {
        int kk = i >> 10, ln = (i >> 5) & 31, j = i & 31;
        s.w[kk][ln][j] = g_wperm[i];
    }
    if (tid < 128) {
        s.bias[tid]  = bias[tid];
        s.gamma[tid] = gamma[tid];
        s.beta[tid]  = beta[tid];
    }

    float c[16][4];
    #pragma unroll
    for (int nt = 0; nt < 16; nt++)
        #pragma unroll
        for (int j = 0; j < 4; j++) c[nt][j] = 0.f;

    int rowBase = blockIdx.x * 128;

    #pragma unroll
    for (int phase = 0; phase < 2; ++phase) {
        const float4* __restrict__ A4 = (const float4*)(phase ? Hin : (const float*)g_agg);
        __syncthreads();
        // load A tile 128x128 (zero-fill past N)
        #pragma unroll
        for (int i = 0; i < 16; i++) {
            int f = tid + i * 256;
            int row = f >> 5, c4 = f & 31;
            int grow = rowBase + row;
            float4 v = (grow < NN) ? __ldg(&A4[grow * 32 + c4]) : make_float4(0.f, 0.f, 0.f, 0.f);
            *(float4*)&s.a[row][c4 * 4] = v;
        }
        __syncthreads();

        int r0 = warp * 16 + g;
        #pragma unroll 4
        for (int kks = 0; kks < 16; kks++) {
            int kk = phase * 16 + kks;
            uint32_t A0 = f2tf32(s.a[r0][kks * 8 + tig]);
            uint32_t A1 = f2tf32(s.a[r0 + 8][kks * 8 + tig]);
            uint32_t A2 = f2tf32(s.a[r0][kks * 8 + tig + 4]);
            uint32_t A3 = f2tf32(s.a[r0 + 8][kks * 8 + tig + 4]);
            const float4* wp = (const float4*)&s.w[kk][lane][0];
            #pragma unroll
            for (int q = 0; q < 8; q++) {
                float4 b = wp[q];
                mma_tf32(c[2 * q],     A0, A1, A2, A3, __float_as_uint(b.x), __float_as_uint(b.y));
                mma_tf32(c[2 * q + 1], A0, A1, A2, A3, __float_as_uint(b.z), __float_as_uint(b.w));
            }
        }
    }

    // ------------- epilogue -------------
    int rA = rowBase + warp * 16 + g;
    int rB = rA + 8;

    #pragma unroll
    for (int nt = 0; nt < 16; nt++) {
        int col = nt * 8 + 2 * tig;
        float b0 = s.bias[col], b1 = s.bias[col + 1];
        c[nt][0] += b0; c[nt][1] += b1;
        c[nt][2] += b0; c[nt][3] += b1;
    }
    if (do_resid) {
        if (rA < NN) {
            #pragma unroll
            for (int nt = 0; nt < 16; nt++) {
                int col = nt * 8 + 2 * tig;
                float2 r = *(const float2*)(Hin + rA * 128 + col);
                c[nt][0] += r.x; c[nt][1] += r.y;
            }
        }
        if (rB < NN) {
            #pragma unroll
            for (int nt = 0; nt < 16; nt++) {
                int col = nt * 8 + 2 * tig;
                float2 r = *(const float2*)(Hin + rB * 128 + col);
                c[nt][2] += r.x; c[nt][3] += r.y;
            }
        }
    }
    if (do_ln) {
        float sA = 0.f, qA = 0.f, sB = 0.f, qB = 0.f;
        #pragma unroll
        for (int nt = 0; nt < 16; nt++) {
            #pragma unroll
            for (int j = 0; j < 4; j++) c[nt][j] = fmaxf(c[nt][j], 0.f);
            sA += c[nt][0] + c[nt][1];
            qA += c[nt][0] * c[nt][0] + c[nt][1] * c[nt][1];
            sB += c[nt][2] + c[nt][3];
            qB += c[nt][2] * c[nt][2] + c[nt][3] * c[nt][3];
        }
        #pragma unroll
        for (int m = 1; m < 4; m <<= 1) {
            sA += __shfl_xor_sync(0xffffffffu, sA, m);
            qA += __shfl_xor_sync(0xffffffffu, qA, m);
            sB += __shfl_xor_sync(0xffffffffu, sB, m);
            qB += __shfl_xor_sync(0xffffffffu, qB, m);
        }
        float muA = sA * (1.f / 128.f);
        float vA = qA * (1.f / 128.f) - muA * muA;
        float rsA = rsqrtf(vA + LN_EPS);
        float muB = sB * (1.f / 128.f);
        float vB = qB * (1.f / 128.f) - muB * muB;
        float rsB = rsqrtf(vB + LN_EPS);
        #pragma unroll
        for (int nt = 0; nt < 16; nt++) {
            int col = nt * 8 + 2 * tig;
            float g0 = s.gamma[col], g1 = s.gamma[col + 1];
            float e0 = s.beta[col],  e1 = s.beta[col + 1];
            c[nt][0] = (c[nt][0] - muA) * rsA * g0 + e0;
            c[nt][1] = (c[nt][1] - muA) * rsA * g1 + e1;
            c[nt][2] = (c[nt][2] - muB) * rsB * g0 + e0;
            c[nt][3] = (c[nt][3] - muB) * rsB * g1 + e1;
        }
    }
    if (rA < NN) {
        #pragma unroll
        for (int nt = 0; nt < 16; nt++) {
            int col = nt * 8 + 2 * tig;
            *(float2*)(out + rA * 128 + col) = make_float2(c[nt][0], c[nt][1]);
        }
    }
    if (rB < NN) {
        #pragma unroll
        for (int nt = 0; nt < 16; nt++) {
            int col = nt * 8 + 2 * tig;
            *(float2*)(out + rB * 128 + col) = make_float2(c[nt][2], c[nt][3]);
        }
    }
}

// ---------------- host driver ----------------
extern "C" void kernel_launch(void* const* d_in, const int* in_sizes, int n_in,
                              void* d_out, int out_size) {
    const float* in_feat = (const float*)d_in[0];
    const int*   ei      = (const int*)d_in[1];
    const float* W_rel   = (const float*)d_in[2];
    const float* b_rel   = (const float*)d_in[3];
    const float* W_root  = (const float*)d_in[4];
    const float* gamma   = (const float*)d_in[5];
    const float* beta    = (const float*)d_in[6];
    float* out = (float*)d_out;

    const int* src = ei;
    const int* dst = ei + EE;

    cudaFuncSetAttribute(gemm_kernel, cudaFuncAttributeMaxDynamicSharedMemorySize,
                         (int)sizeof(GSmem));

    float* bufA = nullptr;
    float* bufB = nullptr;
    cudaGetSymbolAddress((void**)&bufA, g_bufA);
    cudaGetSymbolAddress((void**)&bufB, g_bufB);

    // CSR build (once per launch; reused by all 4 layers)
    zero_kernel<<<(NN + 255) / 256, 256>>>();
    hist_kernel<<<(EE + 255) / 256, 256>>>(dst);
    scan_kernel<<<1, 1024>>>();
    scatter_kernel<<<(EE + 255) / 256, 256>>>(src, dst);

    const int gemm_grid = (NN + 127) / 128;  // 782
    const float* hin = in_feat;
    for (int l = 0; l < LL; l++) {
        wprep_kernel<<<128, 256>>>(W_rel + l * DD * DD, W_root + l * DD * DD);
        agg_kernel<<<(NN * 32 + 255) / 256, 256>>>(hin);
        float* hout = (l == LL - 1) ? out : ((l & 1) ? bufB : bufA);
        int do_ln = (l < LL - 1) ? 1 : 0;
        int do_resid = (l >= 1 && l <= LL - 2) ? 1 : 0;
        gemm_kernel<<<gemm_grid, 256, sizeof(GSmem)>>>(hin, b_rel + l * DD, gamma, beta,
                                                       hout, do_ln, do_resid);
        hin = hout;
    }
}